// round 4
// baseline (speedup 1.0000x reference)
#include <cuda_runtime.h>
#include <cuda_bf16.h>

typedef unsigned long long ull;

// Problem constants
#define NSEQ 1024
#define HID  100
#define G4   400      // 4*HID
#define WD   100
#define TD   25
#define IN0  125      // WD+TD
#define LBL  40
#define EPSV 1e-20f

// recurrence layout: 800 threads, tid = j*8 + g*2 + p
#define NTHR2 800
#define HALFK 56      // padded half of hidden dim (2*56=112)
#define NW2   28      // ull weights per thread (56 floats)

// ---------------- device scratch ----------------
__device__ float d_Wr0[NW2 * 2 * NTHR2];  // [(m*NTHR2+tid)*2+e]
__device__ float d_Wr1[NW2 * 2 * NTHR2];
__device__ float d_Wt0[IN0 * G4];         // W_ih0 transposed: [k][r]
__device__ float d_Wt1[HID * G4];         // W_ih1 transposed
__device__ float d_G0[NSEQ * G4];
__device__ float d_G1[NSEQ * G4];
__device__ float d_h0[NSEQ * HID];
__device__ float d_h1[NSEQ * HID];
__device__ float d_u[HID];
__device__ float d_v[HID];
__device__ float d_cval;
__device__ float d_ea[NSEQ];
__device__ float d_eb[NSEQ];
__device__ float d_f[NSEQ];
__device__ int   d_sink;

// ---------------- f32x2 helpers ----------------
__device__ __forceinline__ void fma2(ull& d, ull a, ull b) {
    asm("fma.rn.f32x2 %0, %1, %2, %0;" : "+l"(d) : "l"(a), "l"(b));
}
__device__ __forceinline__ void add2(ull& d, ull a, ull b) {
    asm("add.rn.f32x2 %0, %1, %2;" : "=l"(d) : "l"(a), "l"(b));
}
__device__ __forceinline__ float sum2(ull v) {
    unsigned int lo, hi;
    asm("mov.b64 {%0, %1}, %2;" : "=r"(lo), "=r"(hi) : "l"(v));
    return __uint_as_float(lo) + __uint_as_float(hi);
}
__device__ __forceinline__ float tanhfast(float x) {
    float e = __expf(2.f * x);
    return __fdividef(e - 1.f, e + 1.f);
}

// ---------------- prep: weight relayouts ----------------
__global__ void prep_kernel(const float* __restrict__ W_hh0,
                            const float* __restrict__ W_hh1,
                            const float* __restrict__ W_ih0,
                            const float* __restrict__ W_ih1) {
    int idx = blockIdx.x * blockDim.x + threadIdx.x;
    const int n_wr  = NW2 * 2 * NTHR2;  // 44800
    const int n_wt0 = IN0 * G4;         // 50000
    const int n_wt1 = HID * G4;         // 40000
    if (idx < 2 * n_wr) {
        int layer = idx >= n_wr;
        int rel = idx - layer * n_wr;
        int e = rel & 1;
        int lin = rel >> 1;               // m*NTHR2 + tid
        int m = lin / NTHR2, tid = lin % NTHR2;
        int p = tid & 1, g = (tid >> 1) & 3, j = tid >> 3;
        int k = p * HALFK + 2 * m + e;
        const float* W = layer ? W_hh1 : W_hh0;
        float val = (k < HID) ? W[(g * HID + j) * HID + k] : 0.f;
        (layer ? d_Wr1 : d_Wr0)[rel] = val;
    } else if (idx < 2 * n_wr + n_wt0) {
        int rel = idx - 2 * n_wr;
        int k = rel / G4, r = rel % G4;
        d_Wt0[rel] = W_ih0[r * IN0 + k];
    } else if (idx < 2 * n_wr + n_wt0 + n_wt1) {
        int rel = idx - 2 * n_wr - n_wt0;
        int k = rel / G4, r = rel % G4;
        d_Wt1[rel] = W_ih1[r * HID + k];
    }
}

__global__ void noop_kernel() {
    if (threadIdx.x == 1024) d_sink = 1;   // never taken; keeps kernel non-empty
}

// ---------------- G0: emb @ W_ih0^T + biases ----------------
__global__ __launch_bounds__(416) void g0_kernel(
    const int* __restrict__ wi, const int* __restrict__ ti,
    const float* __restrict__ word_table, const float* __restrict__ tag_table,
    const float* __restrict__ b_ih, const float* __restrict__ b_hh) {
    __shared__ float embs[8][IN0 + 3];
    int t0 = blockIdx.x * 8;
    int tid = threadIdx.x;
    for (int idx = tid; idx < 8 * IN0; idx += 416) {
        int tt = idx / IN0, k = idx % IN0;
        int t = t0 + tt;
        embs[tt][k] = (k < WD) ? word_table[wi[t] * WD + k]
                               : tag_table[ti[t] * TD + (k - WD)];
    }
    __syncthreads();
    int r = tid;
    if (r < G4) {
        float bias = b_ih[r] + b_hh[r];
        float acc[8];
#pragma unroll
        for (int tt = 0; tt < 8; tt++) acc[tt] = bias;
#pragma unroll 5
        for (int k = 0; k < IN0; k++) {
            float w = d_Wt0[k * G4 + r];
#pragma unroll
            for (int tt = 0; tt < 8; tt++) acc[tt] += w * embs[tt][k];
        }
#pragma unroll
        for (int tt = 0; tt < 8; tt++) d_G0[(t0 + tt) * G4 + r] = acc[tt];
    }
}

// ---------------- G1: h0 @ W_ih1^T + biases ----------------
__global__ __launch_bounds__(416) void g1_kernel(
    const float* __restrict__ b_ih, const float* __restrict__ b_hh) {
    __shared__ float embs[8][HID + 4];
    int t0 = blockIdx.x * 8;
    int tid = threadIdx.x;
    for (int idx = tid; idx < 8 * HID; idx += 416) {
        int tt = idx / HID, k = idx % HID;
        embs[tt][k] = d_h0[(t0 + tt) * HID + k];
    }
    __syncthreads();
    int r = tid;
    if (r < G4) {
        float bias = b_ih[r] + b_hh[r];
        float acc[8];
#pragma unroll
        for (int tt = 0; tt < 8; tt++) acc[tt] = bias;
#pragma unroll 4
        for (int k = 0; k < HID; k++) {
            float w = d_Wt1[k * G4 + r];
#pragma unroll
            for (int tt = 0; tt < 8; tt++) acc[tt] += w * embs[tt][k];
        }
#pragma unroll
        for (int tt = 0; tt < 8; tt++) d_G1[(t0 + tt) * G4 + r] = acc[tt];
    }
}

// ---------------- persistent single-CTA LSTM recurrence (split-k) ----------------
// tid = j*8 + g*2 + p : j = unit (0..99), g = gate (i,f,g,o), p = k-half
// Each thread computes a 56-wide half dot product: 14 LDS.128 + 28 FFMA2.
__global__ void __launch_bounds__(NTHR2, 1) rec_kernel(int layer) {
    __shared__ __align__(16) float hs[2][2 * HALFK];  // 112 floats per buffer
    const ull* __restrict__ Wr =
        reinterpret_cast<const ull*>(layer ? d_Wr1 : d_Wr0);
    const float* __restrict__ G = layer ? d_G1 : d_G0;
    float* __restrict__ hout    = layer ? d_h1 : d_h0;

    int tid = threadIdx.x;
    int p = tid & 1, g = (tid >> 1) & 3, j = tid >> 3;
    int gidx = g * HID + j;
    bool loader = (p == 0);

    // register-resident half-row of W_hh (56 floats = 28 f32x2)
    ull w[NW2];
#pragma unroll
    for (int m = 0; m < NW2; m++) w[m] = Wr[m * NTHR2 + tid];

    if (tid < 4 * HALFK) ((float*)hs)[tid] = 0.f;
    float c = 0.f;
    float gin = loader ? G[gidx] : 0.f;
    unsigned base8 = (tid & 31) & ~7u;
    __syncthreads();

    for (int t = 0; t < NSEQ; t++) {
        // prefetch next step's input preactivation (one-step slack hides L2)
        float gnext = loader ? __ldg(G + min(t + 1, NSEQ - 1) * G4 + gidx) : 0.f;

        // this thread's 56-float half of h: 14 x LDS.128 (p*14 ulonglong2 = p*56 floats)
        const ulonglong2* __restrict__ h2 =
            reinterpret_cast<const ulonglong2*>(hs[t & 1]) + p * 14;
        ull a0 = 0ull, a1 = 0ull, a2 = 0ull, a3 = 0ull;
#pragma unroll
        for (int m = 0; m < 14; m += 2) {          // m = 0,2,4,6,8,10,12
            ulonglong2 x = h2[m];
            fma2(a0, w[2 * m], x.x);
            fma2(a1, w[2 * m + 1], x.y);
        }
#pragma unroll
        for (int m = 1; m < 14; m += 2) {          // m = 1,3,5,7,9,11,13
            ulonglong2 x = h2[m];
            fma2(a2, w[2 * m], x.x);
            fma2(a3, w[2 * m + 1], x.y);
        }
        add2(a0, a0, a2);
        add2(a1, a1, a3);
        add2(a0, a0, a1);
        float part = sum2(a0) + gin;               // gin only on p==0 half
        float pre = part + __shfl_xor_sync(0xffffffffu, part, 1);

        // branchless activation: g==2 -> tanh, else sigmoid
        float xin = (g == 2) ? 2.f * pre : -pre;
        float e = __expf(xin);
        float num = (g == 2) ? (e - 1.f) : 1.f;
        float act = __fdividef(num, e + 1.f);

        // gather the 4 gates of this unit (8-lane aligned group, stride 2)
        float vi = __shfl_sync(0xffffffffu, act, base8 + 0);
        float vf = __shfl_sync(0xffffffffu, act, base8 + 2);
        float vg = __shfl_sync(0xffffffffu, act, base8 + 4);
        float vo = __shfl_sync(0xffffffffu, act, base8 + 6);

        // all 8 threads of a unit compute c,h redundantly; one stores
        c = vf * c + vi * vg;
        float h = vo * tanhfast(c);
        if ((tid & 7) == 0) {
            hs[(t + 1) & 1][j] = h;
            hout[t * HID + j] = h;
        }
        gin = gnext;
        __syncthreads();
    }
}

// ---------------- rank-1 collapse of the pairwise scorer ----------------
__global__ void uv_kernel(const float* __restrict__ W_h2h,
                          const float* __restrict__ b_h2h,
                          const float* __restrict__ W_sc,
                          const float* __restrict__ b_sc) {
    int q = threadIdx.x;
    if (q < HID) {
        float u = 0.f, v = 0.f;
        for (int pp = 0; pp < HID; pp++) {
            float s = W_sc[pp];
            u += s * W_h2h[pp * (2 * HID) + q];
            v += s * W_h2h[pp * (2 * HID) + HID + q];
        }
        d_u[q] = u;
        d_v[q] = v;
    }
    if (q == HID) {
        float cc = b_sc[0];
        for (int pp = 0; pp < HID; pp++) cc += W_sc[pp] * b_h2h[pp];
        d_cval = cc;
    }
}

__global__ void ab_kernel() {
    int i = blockIdx.x * blockDim.x + threadIdx.x;
    if (i >= NSEQ) return;
    const float* h = &d_h1[i * HID];
    float a = 0.f, b = 0.f;
#pragma unroll 4
    for (int q = 0; q < HID; q++) {
        float hv = h[q];
        a += hv * d_u[q];
        b += hv * d_v[q];
    }
    d_ea[i] = __expf(a);
    d_eb[i] = __expf(b + d_cval);
}

__global__ void sf_kernel() {
    __shared__ float red[NSEQ];
    int t = threadIdx.x;
    red[t] = d_ea[t];
    __syncthreads();
    for (int s = NSEQ / 2; s > 32; s >>= 1) {
        if (t < s) red[t] += red[t + s];
        __syncthreads();
    }
    if (t < 32) {
        float x = red[t] + red[t + 32];
        for (int o = 16; o > 0; o >>= 1)
            x += __shfl_down_sync(0xffffffffu, x, o);
        if (t == 0) red[0] = x;
    }
    __syncthreads();
    float S = red[0];
    float e = d_eb[t];
    d_f[t] = __fdividef(e, e * S + EPSV);
}

// one block per row; float4 stores for the 4MB HBM write
__global__ __launch_bounds__(256) void scores_kernel(float* __restrict__ out) {
    int i = blockIdx.x;
    float eai = d_ea[i];
    const float4* f4 = reinterpret_cast<const float4*>(d_f);
    float4* o4 = reinterpret_cast<float4*>(out + (size_t)i * NSEQ);
    int jj = threadIdx.x;
    float4 v = f4[jj];
    v.x *= eai; v.y *= eai; v.z *= eai; v.w *= eai;
    o4[jj] = v;
}

__global__ void labels_kernel(const float* __restrict__ W_lab,
                              const float* __restrict__ b_lab,
                              float* __restrict__ out) {
    __shared__ float hrow[HID];
    __shared__ float el[LBL];
    __shared__ float denom;
    int t = blockIdx.x;  // 0..NSEQ-2, uses h[t+1]
    int tid = threadIdx.x;
    if (tid < HID) hrow[tid] = d_h1[(t + 1) * HID + tid];
    __syncthreads();
    if (tid < LBL) {
        float a = b_lab[tid];
        for (int q = 0; q < HID; q++) a += hrow[q] * W_lab[tid * HID + q];
        el[tid] = __expf(a);
    }
    __syncthreads();
    if (tid == 0) {
        float s = 0.f;
        for (int l = 0; l < LBL; l++) s += el[l];
        denom = s + EPSV;
    }
    __syncthreads();
    if (tid < LBL) out[NSEQ * NSEQ + t * LBL + tid] = el[tid] / denom;
}

// ---------------- launch ----------------
extern "C" void kernel_launch(void* const* d_in, const int* in_sizes, int n_in,
                              void* d_out, int out_size) {
    const int*   wi         = (const int*)d_in[0];
    const int*   ti         = (const int*)d_in[1];
    const float* word_table = (const float*)d_in[2];
    const float* tag_table  = (const float*)d_in[3];
    const float* W_ih0      = (const float*)d_in[4];
    const float* W_hh0      = (const float*)d_in[5];
    const float* b_ih0      = (const float*)d_in[6];
    const float* b_hh0      = (const float*)d_in[7];
    const float* W_ih1      = (const float*)d_in[8];
    const float* W_hh1      = (const float*)d_in[9];
    const float* b_ih1      = (const float*)d_in[10];
    const float* b_hh1      = (const float*)d_in[11];
    const float* W_h2h      = (const float*)d_in[12];
    const float* b_h2h      = (const float*)d_in[13];
    const float* W_sc       = (const float*)d_in[14];
    const float* b_sc       = (const float*)d_in[15];
    const float* W_lab      = (const float*)d_in[16];
    const float* b_lab      = (const float*)d_in[17];
    float* out = (float*)d_out;

    const int prep_total = 2 * (NW2 * 2 * NTHR2) + IN0 * G4 + HID * G4;
    prep_kernel<<<(prep_total + 255) / 256, 256>>>(W_hh0, W_hh1, W_ih0, W_ih1);  // idx 0
    g0_kernel<<<NSEQ / 8, 416>>>(wi, ti, word_table, tag_table, b_ih0, b_hh0);   // idx 1
    noop_kernel<<<1, 32>>>();                                                    // idx 2
    rec_kernel<<<1, NTHR2>>>(0);                                                 // idx 3 (profiled)
    g1_kernel<<<NSEQ / 8, 416>>>(b_ih1, b_hh1);                                  // idx 4
    rec_kernel<<<1, NTHR2>>>(1);                                                 // idx 5
    uv_kernel<<<1, 128>>>(W_h2h, b_h2h, W_sc, b_sc);
    ab_kernel<<<NSEQ / 256, 256>>>();
    sf_kernel<<<1, NSEQ>>>();
    scores_kernel<<<NSEQ, 256>>>(out);
    labels_kernel<<<NSEQ - 1, 128>>>(W_lab, b_lab, out);
}

// round 9
// speedup vs baseline: 2.0127x; 2.0127x over previous
#include <cuda_runtime.h>
#include <cuda_bf16.h>

typedef unsigned long long ull;

// Problem constants
#define NSEQ 1024
#define HID  100
#define G4   400      // 4*HID
#define WD   100
#define TD   25
#define IN0  125      // WD+TD
#define LBL  40
#define NTHR 416      // 104 padded units * 4 gates
#define EPSV 1e-20f

// ---------------- device scratch (no allocations allowed) ----------------
__device__ float d_Wr0[HID * NTHR];   // recurrent weights layer0, [k][tid]
__device__ float d_Wr1[HID * NTHR];
__device__ float d_Wt0[IN0 * G4];     // W_ih0 transposed: [k][r]
__device__ float d_G0[NSEQ * G4];     // input preactivations layer0
__device__ float d_G1[NSEQ * G4];     // produced by streamers during pipeline
__device__ float d_h0[NSEQ * HID];
__device__ float d_h1[NSEQ * HID];
__device__ float d_u[HID];
__device__ float d_v[HID];
__device__ float d_cval;
__device__ float d_ea[NSEQ];
__device__ float d_eb[NSEQ];
__device__ float d_f[NSEQ];
__device__ int   d_prog0;             // last h0 row published by rec0
__device__ int   d_prog1[4];          // last G1 row published per streamer
__device__ int   d_sink;

// ---------------- helpers ----------------
__device__ __forceinline__ void fma2(ull& d, ull a, ull b) {
    asm("fma.rn.f32x2 %0, %1, %2, %0;" : "+l"(d) : "l"(a), "l"(b));
}
__device__ __forceinline__ void add2(ull& d, ull a, ull b) {
    asm("add.rn.f32x2 %0, %1, %2;" : "=l"(d) : "l"(a), "l"(b));
}
__device__ __forceinline__ ull pack2(float lo, float hi) {
    ull r;
    unsigned int ulo = __float_as_uint(lo), uhi = __float_as_uint(hi);
    asm("mov.b64 %0, {%1, %2};" : "=l"(r) : "r"(ulo), "r"(uhi));
    return r;
}
__device__ __forceinline__ float sum2(ull v) {
    unsigned int lo, hi;
    asm("mov.b64 {%0, %1}, %2;" : "=r"(lo), "=r"(hi) : "l"(v));
    return __uint_as_float(lo) + __uint_as_float(hi);
}
__device__ __forceinline__ float tanhfast(float x) {
    float e = __expf(2.f * x);
    return __fdividef(e - 1.f, e + 1.f);
}
__device__ __forceinline__ int ldacq(const int* p) {
    int v;
    asm volatile("ld.acquire.gpu.global.b32 %0, [%1];" : "=r"(v) : "l"(p) : "memory");
    return v;
}
__device__ __forceinline__ void strel(int* p, int v) {
    asm volatile("st.release.gpu.global.b32 [%0], %1;" :: "l"(p), "r"(v) : "memory");
}

// ---------------- prep: weight relayouts + flag reset ----------------
__global__ void prep_kernel(const float* __restrict__ W_hh0,
                            const float* __restrict__ W_hh1,
                            const float* __restrict__ W_ih0) {
    int idx = blockIdx.x * blockDim.x + threadIdx.x;
    const int n_wr  = HID * NTHR;       // 41600
    const int n_wt0 = IN0 * G4;         // 50000
    if (idx == 0) {                      // reset pipeline flags every replay
        d_prog0 = -1;
        d_prog1[0] = d_prog1[1] = d_prog1[2] = d_prog1[3] = -1;
    }
    if (idx < n_wr) {
        int k = idx / NTHR, t = idx % NTHR;
        int j = t >> 2, g = t & 3;
        d_Wr0[idx] = (j < HID) ? W_hh0[(g * HID + j) * HID + k] : 0.f;
    } else if (idx < 2 * n_wr) {
        int rel = idx - n_wr;
        int k = rel / NTHR, t = rel % NTHR;
        int j = t >> 2, g = t & 3;
        d_Wr1[rel] = (j < HID) ? W_hh1[(g * HID + j) * HID + k] : 0.f;
    } else if (idx < 2 * n_wr + n_wt0) {
        int rel = idx - 2 * n_wr;
        int k = rel / G4, r = rel % G4;
        d_Wt0[rel] = W_ih0[r * IN0 + k];
    }
}

__global__ void noop_kernel() {
    if (threadIdx.x == 1024) d_sink = 1;   // never taken
}

// ---------------- G0: emb @ W_ih0^T + biases (parallel over t) ----------------
__global__ __launch_bounds__(NTHR) void g0_kernel(
    const int* __restrict__ wi, const int* __restrict__ ti,
    const float* __restrict__ word_table, const float* __restrict__ tag_table,
    const float* __restrict__ b_ih, const float* __restrict__ b_hh) {
    __shared__ float embs[8][IN0 + 3];
    int t0 = blockIdx.x * 8;
    int tid = threadIdx.x;
    for (int idx = tid; idx < 8 * IN0; idx += NTHR) {
        int tt = idx / IN0, k = idx % IN0;
        int t = t0 + tt;
        embs[tt][k] = (k < WD) ? word_table[wi[t] * WD + k]
                               : tag_table[ti[t] * TD + (k - WD)];
    }
    __syncthreads();
    int r = tid;
    if (r < G4) {
        float bias = b_ih[r] + b_hh[r];
        float acc[8];
#pragma unroll
        for (int tt = 0; tt < 8; tt++) acc[tt] = bias;
#pragma unroll 5
        for (int k = 0; k < IN0; k++) {
            float w = d_Wt0[k * G4 + r];
#pragma unroll
            for (int tt = 0; tt < 8; tt++) acc[tt] += w * embs[tt][k];
        }
#pragma unroll
        for (int tt = 0; tt < 8; tt++) d_G0[(t0 + tt) * G4 + r] = acc[tt];
    }
}

// ---------------- recurrence (one CTA, R2-proven layout + LDS.128) ----------------
// tid = j*4 + g : j = hidden unit (0..103 padded), g = gate i/f/g/o
__device__ __forceinline__ void rec_run(const float* __restrict__ Wr,
                                        const float* __restrict__ G,
                                        float* __restrict__ hout,
                                        bool publish, bool waitg) {
    __shared__ __align__(16) float hs[2][112];
    int tid = threadIdx.x;
    int g = tid & 3, j = tid >> 2;
    bool active = (j < HID);
    int gidx = g * HID + j;

    // register-resident W_hh row: 100 floats packed as 50 f32x2
    ull w2[50];
#pragma unroll
    for (int k = 0; k < 50; k++)
        w2[k] = pack2(Wr[(2 * k) * NTHR + tid], Wr[(2 * k + 1) * NTHR + tid]);

    if (tid < 224) ((float*)hs)[tid] = 0.f;
    float c = 0.f;
    // cached progress per streamer (rec1 only)
    int s0 = -1, s1 = -1, s2 = -1, s3 = -1;
    if (waitg) {
        int v;
        do { v = ldacq(&d_prog1[0]); } while (v < 0);
        s0 = v;
    }
    float gin = active ? (waitg ? __ldcg(&G[gidx]) : __ldg(&G[gidx])) : 0.f;
    unsigned lanebase = (tid & 31) & ~3u;
    __syncthreads();

    for (int t = 0; t < NSEQ; t++) {
        const ulonglong2* __restrict__ h2 =
            reinterpret_cast<const ulonglong2*>(hs[t & 1]);
        ull a0 = 0ull, a1 = 0ull, a2 = 0ull, a3 = 0ull;
#pragma unroll
        for (int m = 0; m < 25; m++) {
            ulonglong2 x = h2[m];
            if (m & 1) { fma2(a2, w2[2 * m], x.x); fma2(a3, w2[2 * m + 1], x.y); }
            else       { fma2(a0, w2[2 * m], x.x); fma2(a1, w2[2 * m + 1], x.y); }
        }
        add2(a0, a0, a2);
        add2(a1, a1, a3);
        add2(a0, a0, a1);
        float pre = sum2(a0) + gin;

        // branchless activation: g==2 -> tanh, else sigmoid
        float xin = (g == 2) ? 2.f * pre : -pre;
        float e = __expf(xin);
        float num = (g == 2) ? (e - 1.f) : 1.f;
        float act = __fdividef(num, e + 1.f);

        float vi = __shfl_sync(0xffffffffu, act, lanebase + 0);
        float vf = __shfl_sync(0xffffffffu, act, lanebase + 1);
        float vg = __shfl_sync(0xffffffffu, act, lanebase + 2);
        float vo = __shfl_sync(0xffffffffu, act, lanebase + 3);

        if (g == 0) {
            c = vf * c + vi * vg;
            float h = vo * tanhfast(c);
            hs[(t + 1) & 1][j] = h;
            if (active) hout[t * HID + j] = h;
        }

        // prefetch next G row (pipeline-gated for rec1)
        int tn = (t + 1 < NSEQ) ? t + 1 : NSEQ - 1;
        if (waitg && t + 1 < NSEQ) {
            int ss = tn & 3;
            int seen = (ss == 0) ? s0 : (ss == 1) ? s1 : (ss == 2) ? s2 : s3;
            if (seen < tn) {
                int v;
                do { v = ldacq(&d_prog1[ss]); } while (v < tn);
                if (ss == 0) s0 = v; else if (ss == 1) s1 = v;
                else if (ss == 2) s2 = v; else s3 = v;
            }
        }
        float gnext = active ? (waitg ? __ldcg(&G[tn * G4 + gidx])
                                      : __ldg(&G[tn * G4 + gidx])) : 0.f;
        __syncthreads();
        gin = gnext;
        // release store is cumulative over the happens-before established by
        // the __syncthreads above: all threads' h writes for step t are visible
        if (publish && tid == 0) strel(&d_prog0, t);
    }
}

// ---------------- streamer: G1[t] = W_ih1 . h0[t] + biases, t = s mod 4 ----------------
__device__ __forceinline__ void streamer_run(const float* __restrict__ W_ih1,
                                             const float* __restrict__ b_ih1,
                                             const float* __restrict__ b_hh1,
                                             int s) {
    __shared__ __align__(16) float sh[100];
    int tid = threadIdx.x;
    bool act = tid < G4;

    // register-resident W_ih1 row (100 contiguous floats, 16B-aligned)
    ulonglong2 w[25];
    if (act) {
        const ulonglong2* wp = reinterpret_cast<const ulonglong2*>(W_ih1 + tid * HID);
#pragma unroll
        for (int m = 0; m < 25; m++) w[m] = wp[m];
    }
    float bias = act ? b_ih1[tid] + b_hh1[tid] : 0.f;
    int seen = -1;

    for (int t = s; t < NSEQ; t += 4) {
        if (tid == 0 && seen < t) {
            int v;
            do { v = ldacq(&d_prog0); } while (v < t);
            seen = v;
        }
        __syncthreads();                 // orders h0 reads after the acquire
        if (tid < HID) sh[tid] = __ldcg(&d_h0[t * HID + tid]);
        __syncthreads();
        if (act) {
            const ulonglong2* __restrict__ h2 =
                reinterpret_cast<const ulonglong2*>(sh);
            ull a0 = 0ull, a1 = 0ull, a2 = 0ull, a3 = 0ull;
#pragma unroll
            for (int m = 0; m < 25; m++) {
                ulonglong2 x = h2[m];
                if (m & 1) { fma2(a2, w[m].x, x.x); fma2(a3, w[m].y, x.y); }
                else       { fma2(a0, w[m].x, x.x); fma2(a1, w[m].y, x.y); }
            }
            add2(a0, a0, a2);
            add2(a1, a1, a3);
            add2(a0, a0, a1);
            d_G1[t * G4 + tid] = bias + sum2(a0);
        }
        __syncthreads();
        if (tid == 0) strel(&d_prog1[s], t);
    }
}

// ---------------- fused pipeline kernel: 6 persistent CTAs ----------------
__global__ void __launch_bounds__(NTHR, 1) fused_kernel(
        const float* __restrict__ W_ih1,
        const float* __restrict__ b_ih1,
        const float* __restrict__ b_hh1) {
    int b = blockIdx.x;
    if (b == 0)      rec_run(d_Wr0, d_G0, d_h0, true,  false);
    else if (b == 1) rec_run(d_Wr1, d_G1, d_h1, false, true);
    else             streamer_run(W_ih1, b_ih1, b_hh1, b - 2);
}

// ---------------- rank-1 collapse of the pairwise scorer ----------------
__global__ void uv_kernel(const float* __restrict__ W_h2h,
                          const float* __restrict__ b_h2h,
                          const float* __restrict__ W_sc,
                          const float* __restrict__ b_sc) {
    int q = threadIdx.x;
    if (q < HID) {
        float u = 0.f, v = 0.f;
        for (int pp = 0; pp < HID; pp++) {
            float s = W_sc[pp];
            u += s * W_h2h[pp * (2 * HID) + q];
            v += s * W_h2h[pp * (2 * HID) + HID + q];
        }
        d_u[q] = u;
        d_v[q] = v;
    }
    if (q == HID) {
        float cc = b_sc[0];
        for (int pp = 0; pp < HID; pp++) cc += W_sc[pp] * b_h2h[pp];
        d_cval = cc;
    }
}

__global__ void ab_kernel() {
    int i = blockIdx.x * blockDim.x + threadIdx.x;
    if (i >= NSEQ) return;
    const float* h = &d_h1[i * HID];
    float a = 0.f, b = 0.f;
#pragma unroll 4
    for (int q = 0; q < HID; q++) {
        float hv = h[q];
        a += hv * d_u[q];
        b += hv * d_v[q];
    }
    d_ea[i] = __expf(a);
    d_eb[i] = __expf(b + d_cval);
}

__global__ void sf_kernel() {
    __shared__ float red[NSEQ];
    int t = threadIdx.x;
    red[t] = d_ea[t];
    __syncthreads();
    for (int s = NSEQ / 2; s > 32; s >>= 1) {
        if (t < s) red[t] += red[t + s];
        __syncthreads();
    }
    if (t < 32) {
        float x = red[t] + red[t + 32];
        for (int o = 16; o > 0; o >>= 1)
            x += __shfl_down_sync(0xffffffffu, x, o);
        if (t == 0) red[0] = x;
    }
    __syncthreads();
    float S = red[0];
    float e = d_eb[t];
    d_f[t] = __fdividef(e, e * S + EPSV);
}

// one block per row; float4 stores for the 4MB HBM write
__global__ __launch_bounds__(256) void scores_kernel(float* __restrict__ out) {
    int i = blockIdx.x;
    float eai = d_ea[i];
    const float4* f4 = reinterpret_cast<const float4*>(d_f);
    float4* o4 = reinterpret_cast<float4*>(out + (size_t)i * NSEQ);
    int jj = threadIdx.x;
    float4 v = f4[jj];
    v.x *= eai; v.y *= eai; v.z *= eai; v.w *= eai;
    o4[jj] = v;
}

__global__ void labels_kernel(const float* __restrict__ W_lab,
                              const float* __restrict__ b_lab,
                              float* __restrict__ out) {
    __shared__ float hrow[HID];
    __shared__ float el[LBL];
    __shared__ float denom;
    int t = blockIdx.x;  // 0..NSEQ-2, uses h[t+1]
    int tid = threadIdx.x;
    if (tid < HID) hrow[tid] = d_h1[(t + 1) * HID + tid];
    __syncthreads();
    if (tid < LBL) {
        float a = b_lab[tid];
        for (int q = 0; q < HID; q++) a += hrow[q] * W_lab[tid * HID + q];
        el[tid] = __expf(a);
    }
    __syncthreads();
    if (tid == 0) {
        float s = 0.f;
        for (int l = 0; l < LBL; l++) s += el[l];
        denom = s + EPSV;
    }
    __syncthreads();
    if (tid < LBL) out[NSEQ * NSEQ + t * LBL + tid] = el[tid] / denom;
}

// ---------------- launch ----------------
extern "C" void kernel_launch(void* const* d_in, const int* in_sizes, int n_in,
                              void* d_out, int out_size) {
    const int*   wi         = (const int*)d_in[0];
    const int*   ti         = (const int*)d_in[1];
    const float* word_table = (const float*)d_in[2];
    const float* tag_table  = (const float*)d_in[3];
    const float* W_ih0      = (const float*)d_in[4];
    const float* W_hh0      = (const float*)d_in[5];
    const float* b_ih0      = (const float*)d_in[6];
    const float* b_hh0      = (const float*)d_in[7];
    const float* W_ih1      = (const float*)d_in[8];
    const float* W_hh1      = (const float*)d_in[9];
    const float* b_ih1      = (const float*)d_in[10];
    const float* b_hh1      = (const float*)d_in[11];
    const float* W_h2h      = (const float*)d_in[12];
    const float* b_h2h      = (const float*)d_in[13];
    const float* W_sc       = (const float*)d_in[14];
    const float* b_sc       = (const float*)d_in[15];
    const float* W_lab      = (const float*)d_in[16];
    const float* b_lab      = (const float*)d_in[17];
    float* out = (float*)d_out;

    const int prep_total = 2 * (HID * NTHR) + IN0 * G4;
    prep_kernel<<<(prep_total + 255) / 256, 256>>>(W_hh0, W_hh1, W_ih0);       // idx 0
    g0_kernel<<<NSEQ / 8, NTHR>>>(wi, ti, word_table, tag_table, b_ih0, b_hh0); // idx 1
    noop_kernel<<<1, 32>>>();                                                   // idx 2
    noop_kernel<<<1, 32>>>();                                                   // idx 3
    noop_kernel<<<1, 32>>>();                                                   // idx 4
    fused_kernel<<<6, NTHR>>>(W_ih1, b_ih1, b_hh1);                             // idx 5 (profiled)
    uv_kernel<<<1, 128>>>(W_h2h, b_h2h, W_sc, b_sc);
    ab_kernel<<<NSEQ / 256, 256>>>();
    sf_kernel<<<1, NSEQ>>>();
    scores_kernel<<<NSEQ, 256>>>(out);
    labels_kernel<<<NSEQ - 1, 128>>>(W_lab, b_lab, out);
}